// round 15
// baseline (speedup 1.0000x reference)
#include <cuda_runtime.h>
#include <math.h>

#define BSZ 2048
#define ND 128
#define HID 256
#define SHD 64
#define NSTEPS 8
#define MROWS 8
#define NBLOCKS (BSZ / MROWS)
#define NTHR 256

typedef unsigned long long ull;

// ---------- packed f32x2 helpers ----------
__device__ __forceinline__ void fma2(ull &c, ull a, ull b) {
    asm("fma.rn.f32x2 %0, %1, %2, %3;" : "=l"(c) : "l"(a), "l"(b), "l"(c));
}
__device__ __forceinline__ ull packdup(float x) {
    ull r; asm("mov.b64 %0, {%1, %2};" : "=l"(r) : "f"(x), "f"(x)); return r;
}
__device__ __forceinline__ void unpack2(ull v, float &x, float &y) {
    asm("mov.b64 {%0, %1}, %2;" : "=f"(x), "=f"(y) : "l"(v));
}

// ---------- swizzled 16B-chunk shared layout ----------
#define CSW(ci) ((ci) ^ (((ci) >> 3) & 7))
__device__ __forceinline__ ulonglong2 ldchunk_u(const float* buf, int ci) {
    return reinterpret_cast<const ulonglong2*>(buf)[CSW(ci)];
}
__device__ __forceinline__ float4 ldchunk_f(const float* buf, int ci) {
    return reinterpret_cast<const float4*>(buf)[CSW(ci)];
}
__device__ __forceinline__ void stchunk_f(float* buf, int ci, float4 v) {
    reinterpret_cast<float4*>(buf)[CSW(ci)] = v;
}
__device__ __forceinline__ void load_row8(const float* buf, int r, float v[8]) {
    float4 c0 = ldchunk_f(buf, 2 * r);
    float4 c1 = ldchunk_f(buf, 2 * r + 1);
    v[0]=c0.x; v[1]=c0.y; v[2]=c0.z; v[3]=c0.w;
    v[4]=c1.x; v[5]=c1.y; v[6]=c1.z; v[7]=c1.w;
}
__device__ __forceinline__ void store_row8(float* buf, int r, const float v[8]) {
    stchunk_f(buf, 2 * r,     make_float4(v[0], v[1], v[2], v[3]));
    stchunk_f(buf, 2 * r + 1, make_float4(v[4], v[5], v[6], v[7]));
}

// ---------- fast transcendentals ----------
__device__ __forceinline__ float fast_tanh(float x) {
    float z = __expf(2.0f * x);
    return 1.0f - 2.0f / (z + 1.0f);
}
__device__ __forceinline__ float fast_softplus(float x) {
    float z = __expf(-fabsf(x));
    return fmaxf(x, 0.0f) + __logf(1.0f + z);
}
__device__ __forceinline__ float san(float x) { return isfinite(x) ? x : 0.f; }

// ---------- 4-col x 4-row accumulate ----------
__device__ __forceinline__ void acc44(ull acc[8], const float* in_buf, int k, int h, float4 wv) {
    ulonglong2 p = ldchunk_u(in_buf, 2 * k + h);
    fma2(acc[0], p.x, packdup(wv.x)); fma2(acc[1], p.y, packdup(wv.x));
    fma2(acc[2], p.x, packdup(wv.y)); fma2(acc[3], p.y, packdup(wv.y));
    fma2(acc[4], p.x, packdup(wv.z)); fma2(acc[5], p.y, packdup(wv.z));
    fma2(acc[6], p.x, packdup(wv.w)); fma2(acc[7], p.y, packdup(wv.w));
}

// 4-col x 4-row GEMM partial. v[c*4+q] = (col j4+c, row 4h+q). KS mult of 4, >= 8.
__device__ __forceinline__ void gaccum44(float v[16], const float* in_buf,
                                         const float* __restrict__ W, int ldw,
                                         int j4, int h, int k0, int KS) {
    ull acc[8];
    #pragma unroll
    for (int p = 0; p < 8; ++p) acc[p] = 0ULL;
    const int wld4 = ldw >> 2;
    const float4* __restrict__ wp = reinterpret_cast<const float4*>(W) + (size_t)k0 * wld4 + (j4 >> 2);
    float4 w[4];
    #pragma unroll
    for (int u = 0; u < 4; ++u) w[u] = wp[(size_t)u * wld4];
    wp += (size_t)4 * wld4;
    for (int kk = 0; kk < KS - 4; kk += 4) {
        float4 wn[4];
        #pragma unroll
        for (int u = 0; u < 4; ++u) wn[u] = wp[(size_t)u * wld4];
        wp += (size_t)4 * wld4;
        #pragma unroll
        for (int u = 0; u < 4; ++u) acc44(acc, in_buf, k0 + kk + u, h, w[u]);
        #pragma unroll
        for (int u = 0; u < 4; ++u) w[u] = wn[u];
    }
    #pragma unroll
    for (int u = 0; u < 4; ++u) acc44(acc, in_buf, k0 + KS - 4 + u, h, w[u]);
    #pragma unroll
    for (int c = 0; c < 4; ++c) {
        unpack2(acc[2*c],     v[c*4+0], v[c*4+1]);
        unpack2(acc[2*c + 1], v[c*4+2], v[c*4+3]);
    }
}
__device__ __forceinline__ void store4(float* buf, int jbase, int h, const float v[16]) {
    #pragma unroll
    for (int c = 0; c < 4; ++c)
        stchunk_f(buf, (jbase + c) * 2 + h, make_float4(v[c*4+0], v[c*4+1], v[c*4+2], v[c*4+3]));
}

// ---------- 8-col x 4-row accumulate ----------
__device__ __forceinline__ void acc84(ull acc[16], const float* in_buf, int k, int h,
                                      float4 wa, float4 wb) {
    ulonglong2 p = ldchunk_u(in_buf, 2 * k + h);
    fma2(acc[0],  p.x, packdup(wa.x)); fma2(acc[1],  p.y, packdup(wa.x));
    fma2(acc[2],  p.x, packdup(wa.y)); fma2(acc[3],  p.y, packdup(wa.y));
    fma2(acc[4],  p.x, packdup(wa.z)); fma2(acc[5],  p.y, packdup(wa.z));
    fma2(acc[6],  p.x, packdup(wa.w)); fma2(acc[7],  p.y, packdup(wa.w));
    fma2(acc[8],  p.x, packdup(wb.x)); fma2(acc[9],  p.y, packdup(wb.x));
    fma2(acc[10], p.x, packdup(wb.y)); fma2(acc[11], p.y, packdup(wb.y));
    fma2(acc[12], p.x, packdup(wb.z)); fma2(acc[13], p.y, packdup(wb.z));
    fma2(acc[14], p.x, packdup(wb.w)); fma2(acc[15], p.y, packdup(wb.w));
}

// 8-col x 4-row GEMM partial, depth-2 prefetch. v[c*4+q], c=0..7. KS mult of 2, >= 4.
__device__ __forceinline__ void gaccum84(float v[32], const float* in_buf,
                                         const float* __restrict__ W, int ldw,
                                         int j8, int h, int k0, int KS) {
    ull acc[16];
    #pragma unroll
    for (int p = 0; p < 16; ++p) acc[p] = 0ULL;
    const int wld4 = ldw >> 2;
    const float4* __restrict__ wp = reinterpret_cast<const float4*>(W) + (size_t)k0 * wld4 + (j8 >> 2);
    float4 wa[2], wb[2];
    #pragma unroll
    for (int u = 0; u < 2; ++u) { wa[u] = wp[(size_t)u * wld4]; wb[u] = wp[(size_t)u * wld4 + 1]; }
    wp += (size_t)2 * wld4;
    for (int kk = 0; kk < KS - 2; kk += 2) {
        float4 na[2], nb[2];
        #pragma unroll
        for (int u = 0; u < 2; ++u) { na[u] = wp[(size_t)u * wld4]; nb[u] = wp[(size_t)u * wld4 + 1]; }
        wp += (size_t)2 * wld4;
        #pragma unroll
        for (int u = 0; u < 2; ++u) acc84(acc, in_buf, k0 + kk + u, h, wa[u], wb[u]);
        #pragma unroll
        for (int u = 0; u < 2; ++u) { wa[u] = na[u]; wb[u] = nb[u]; }
    }
    #pragma unroll
    for (int u = 0; u < 2; ++u) acc84(acc, in_buf, k0 + KS - 2 + u, h, wa[u], wb[u]);
    #pragma unroll
    for (int c = 0; c < 8; ++c) {
        unpack2(acc[2*c],     v[c*4+0], v[c*4+1]);
        unpack2(acc[2*c + 1], v[c*4+2], v[c*4+3]);
    }
}
__device__ __forceinline__ void store8(float* buf, int jbase, int h, const float v[32]) {
    #pragma unroll
    for (int c = 0; c < 8; ++c)
        stchunk_f(buf, (jbase + c) * 2 + h, make_float4(v[c*4+0], v[c*4+1], v[c*4+2], v[c*4+3]));
}

__device__ __forceinline__ void warp_reduce8(float sq[8]) {
    #pragma unroll
    for (int off = 16; off > 0; off >>= 1) {
        #pragma unroll
        for (int m = 0; m < 8; ++m)
            sq[m] += __shfl_down_sync(0xffffffffu, sq[m], off);
    }
}

__global__ void __launch_bounds__(NTHR, 2)
node_kernel(const float* __restrict__ y0, const float* __restrict__ tv,
            const float* __restrict__ noise,
            const float* __restrict__ fw1, const float* __restrict__ fb1,
            const float* __restrict__ fw2, const float* __restrict__ fb2,
            const float* __restrict__ fw3, const float* __restrict__ fb3,
            const float* __restrict__ amw1, const float* __restrict__ amb1,
            const float* __restrict__ amw2, const float* __restrict__ amb2,
            const float* __restrict__ amw3, const float* __restrict__ amb3,
            const float* __restrict__ alw1, const float* __restrict__ alb1,
            const float* __restrict__ alw2, const float* __restrict__ alb2,
            const float* __restrict__ alw3, const float* __restrict__ alb3,
            const float* __restrict__ kw, float* __restrict__ out)
{
    extern __shared__ float smem[];
    float* xs   = smem;              // 1024  [128][8]
    float* h1   = xs + 1024;         // 2048  [256][8]
    float* h2   = h1 + 2048;         // 2048
    float* fo   = h2 + 2048;         // 1024
    float* ko   = fo + 1024;         // 1024
    float* go   = ko + 1024;         // 1024  (f+g)
    float* ubf  = go + 1024;         // 1024
    float* ubg  = ubf + 1024;        // 1024
    float* a1m  = ubg + 1024;        // 512   [64][8]
    float* a1l  = a1m + 512;         // 512
    float* a2m  = a1l + 512;         // 512
    float* a2l  = a2m + 512;         // 512
    float* cb   = a2l + 512;         // 8192  partial scratch [1024][8]
    float* redk = cb + 8192;         // 16
    float* redf = redk + 16;         // 32
    float* redg = redf + 32;         // 32
    float* kn2s = redg + 32;         // 8

    const int tid = threadIdx.x;
    const int r0 = blockIdx.x * MROWS;
    const float dt = tv[1] - tv[0];
    const int ewj = tid & 127;
    const int ewc = tid >> 7;

    // load y0 tile (transposed [128][8], swizzled); emit output step 0
    {
        float a[4];
        #pragma unroll
        for (int q = 0; q < 4; ++q) {
            int m = 4 * ewc + q;
            float val = y0[(size_t)(r0 + m) * ND + ewj];
            out[(size_t)(r0 + m) * ND + ewj] = val;
            a[q] = val;
        }
        stchunk_f(xs, ewj * 2 + ewc, make_float4(a[0], a[1], a[2], a[3]));
    }
    __syncthreads();

    for (int step = 0; step < NSTEPS; ++step) {
        float v[16];
        float nse[4];
        {
            const float* np = noise + (size_t)step * BSZ * ND + (size_t)(r0 + 4 * ewc) * ND + ewj;
            #pragma unroll
            for (int q = 0; q < 4; ++q) nse[q] = np[(size_t)q * ND];
        }

        // ======== Stage A (partials): f1 | k | am1 | al1 — all 8x4, K-split 2; ALL to cb ========
        // cb rows: f1 s*256+col(0-255); k 512+s*128+col(0-127); am1 768+s*64+col(0-63); al1 896+s*64+col
        if (tid < 128) {                       // f1: s warp-group-uniform
            int s = tid >> 6, u = tid & 63, h = u & 1, cg = u >> 1, j8 = 8 * cg;
            float v32[32];
            gaccum84(v32, xs, fw1, HID, j8, h, s * 64, 64);
            store8(cb, s * 256 + j8, h, v32);
        } else if (tid < 192) {                // k: warp 4 -> s0, warp 5 -> s1
            int u0 = tid - 128;
            int s = u0 >> 5, u = u0 & 31, h = u & 1, cg = u >> 1, j8 = 8 * cg;
            float v32[32];
            gaccum84(v32, xs, kw, ND, j8, h, s * 64, 64);
            store8(cb, 512 + s * 128 + j8, h, v32);
        } else {                               // am1/al1: warp 6 -> s0 (both), warp 7 -> s1 (both)
            int u0 = tid - 192;                // 0-63
            int s = u0 >> 5;                   // warp-uniform
            int lane = u0 & 31;
            int isAm = (lane < 16);
            int u = lane & 15, h = u & 1, cg = u >> 1, j8 = 8 * cg;
            const float* W = isAm ? amw1 : alw1;
            float v32[32];
            gaccum84(v32, xs, W, SHD, j8, h, s * 64, 64);
            int base = (isAm ? 768 : 896) + s * 64;
            store8(cb, base + j8, h, v32);
        }
        __syncthreads();

        // ======== Stage A2: combine + activations (256t, 2 cols each) ========
        if (tid < 128) {                       // f1 -> h1
            int j2 = 2 * tid;
            #pragma unroll
            for (int cc = 0; cc < 2; ++cc) {
                int col = j2 + cc;
                float va[8], wa[8];
                load_row8(cb, col, va); load_row8(cb, 256 + col, wa);
                float b = fb1[col];
                #pragma unroll
                for (int m = 0; m < 8; ++m) va[m] = fast_tanh(va[m] + wa[m] + b);
                store_row8(h1, col, va);
            }
        } else if (tid < 192) {                // k -> ko, + ||k||^2 partials
            int t = tid - 128, j2 = 2 * t;
            float sq[8] = {0,0,0,0,0,0,0,0};
            #pragma unroll
            for (int cc = 0; cc < 2; ++cc) {
                int col = j2 + cc;
                float va[8], wa[8];
                load_row8(cb, 512 + col, va); load_row8(cb, 640 + col, wa);
                #pragma unroll
                for (int m = 0; m < 8; ++m) {
                    float x = fast_tanh(va[m] + wa[m]);
                    va[m] = x;
                    sq[m] += x * x;
                }
                store_row8(ko, col, va);
            }
            warp_reduce8(sq);
            if ((tid & 31) == 0) {
                int w = (tid - 128) >> 5;
                #pragma unroll
                for (int m = 0; m < 8; ++m) redk[w * 8 + m] = sq[m];
            }
        } else if (tid < 224) {                // am1 -> a1m
            int t = tid - 192, j2 = 2 * t;
            #pragma unroll
            for (int cc = 0; cc < 2; ++cc) {
                int col = j2 + cc;
                float va[8], wa[8];
                load_row8(cb, 768 + col, va); load_row8(cb, 832 + col, wa);
                float b = amb1[col];
                #pragma unroll
                for (int m = 0; m < 8; ++m) va[m] = fmaxf(va[m] + wa[m] + b, 0.f);
                store_row8(a1m, col, va);
            }
        } else {                               // al1 -> a1l
            int t = tid - 224, j2 = 2 * t;
            #pragma unroll
            for (int cc = 0; cc < 2; ++cc) {
                int col = j2 + cc;
                float va[8], wa[8];
                load_row8(cb, 896 + col, va); load_row8(cb, 960 + col, wa);
                float b = alb1[col];
                #pragma unroll
                for (int m = 0; m < 8; ++m) va[m] = fmaxf(va[m] + wa[m] + b, 0.f);
                store_row8(a1l, col, va);
            }
        }
        __syncthreads();

        // ======== Stage B: f2, 8x4, 4 warp-uniform K-splits; ALL partials to cb ========
        {
            int s = tid >> 6, u = tid & 63, h = u & 1, cg = u >> 1, j8 = 8 * cg;
            float v32[32];
            gaccum84(v32, h1, fw2, HID, j8, h, s * 64, 64);
            store8(cb, s * 256 + j8, h, v32);
        }
        __syncthreads();

        // ======== Stage B2: h2 combine (256t, 1 col each) + finish ||k||^2 ========
        {
            float acc8[8] = {0,0,0,0,0,0,0,0};
            #pragma unroll
            for (int s = 0; s < 4; ++s) {
                float t8[8];
                load_row8(cb, s * 256 + tid, t8);
                #pragma unroll
                for (int m = 0; m < 8; ++m) acc8[m] += t8[m];
            }
            float b = fb2[tid];
            #pragma unroll
            for (int m = 0; m < 8; ++m) acc8[m] = fast_softplus(acc8[m] + b);
            store_row8(h2, tid, acc8);
            if (tid < 8) kn2s[tid] = redk[tid] + redk[8 + tid];
        }
        __syncthreads();

        // ======== Stage C1: f3, 4x4, 4 warp-uniform K-splits; ALL partials to cb ========
        {
            int s = tid >> 6, u = tid & 63, h = u & 1, cg = u >> 1, j4 = 4 * cg;
            gaccum44(v, h2, fw3, ND, j4, h, s * 64, 64);
            store4(cb, s * 128 + j4, h, v);
        }
        __syncthreads();

        // ======== Stage C2: f3 combine (128t) || am2 (32t, 4x4) || al2 (32t, 4x4) ========
        if (tid < 128) {
            float r8[8] = {0,0,0,0,0,0,0,0};
            #pragma unroll
            for (int s = 0; s < 4; ++s) {
                float4 c0 = ldchunk_f(cb, (s * 128 + tid) * 2);
                float4 c1 = ldchunk_f(cb, (s * 128 + tid) * 2 + 1);
                r8[0]+=c0.x; r8[1]+=c0.y; r8[2]+=c0.z; r8[3]+=c0.w;
                r8[4]+=c1.x; r8[5]+=c1.y; r8[6]+=c1.z; r8[7]+=c1.w;
            }
            float b = fb3[tid];
            #pragma unroll
            for (int m = 0; m < 8; ++m) r8[m] += b;
            store_row8(fo, tid, r8);
        } else if (tid < 160) {
            int u = tid - 128, h = u & 1, cg = u >> 1, j4 = 4 * cg;
            gaccum44(v, a1m, amw2, SHD, j4, h, 0, SHD);
            float4 b = reinterpret_cast<const float4*>(amb2)[cg];
            float bb[4] = {b.x, b.y, b.z, b.w};
            #pragma unroll
            for (int c = 0; c < 4; ++c)
                #pragma unroll
                for (int q = 0; q < 4; ++q) v[c*4+q] = fmaxf(v[c*4+q] + bb[c], 0.f);
            store4(a2m, j4, h, v);
        } else if (tid < 192) {
            int u = tid - 160, h = u & 1, cg = u >> 1, j4 = 4 * cg;
            gaccum44(v, a1l, alw2, SHD, j4, h, 0, SHD);
            float4 b = reinterpret_cast<const float4*>(alb2)[cg];
            float bb[4] = {b.x, b.y, b.z, b.w};
            #pragma unroll
            for (int c = 0; c < 4; ++c)
                #pragma unroll
                for (int q = 0; q < 4; ++q) v[c*4+q] = fmaxf(v[c*4+q] + bb[c], 0.f);
            store4(a2l, j4, h, v);
        }
        __syncthreads();

        // ======== Stage C3: am3 (128t, 4x4, Ksplit2) || al3 (128t, 4x4, Ksplit2); partials to cb ========
        if (tid < 128) {
            int s = tid >> 6, u = tid & 63, h = u & 1, cg = u >> 1, j4 = 4 * cg;
            gaccum44(v, a2m, amw3, ND, j4, h, s * 32, 32);
            store4(cb, s * 128 + j4, h, v);
        } else {
            int t = tid - 128, s = t >> 6, u = t & 63, h = u & 1, cg = u >> 1, j4 = 4 * cg;
            gaccum44(v, a2l, alw3, ND, j4, h, s * 32, 32);
            store4(cb, 256 + s * 128 + j4, h, v);
        }
        __syncthreads();

        // ======== Stage E: combine am3/al3, g, f+g, u_f, u_g ========
        {
            float4 kv = ldchunk_f(ko,  ewj * 2 + ewc);
            float4 fv = ldchunk_f(fo,  ewj * 2 + ewc);
            float4 m0 = ldchunk_f(cb, ewj * 2 + ewc);
            float4 m1 = ldchunk_f(cb, (128 + ewj) * 2 + ewc);
            float4 l0 = ldchunk_f(cb, (256 + ewj) * 2 + ewc);
            float4 l1 = ldchunk_f(cb, (384 + ewj) * 2 + ewc);
            float bam = amb3[ewj], bal = alb3[ewj];
            float kk[4] = {kv.x, kv.y, kv.z, kv.w};
            float ff[4] = {fv.x, fv.y, fv.z, fv.w};
            float mm[4] = {m0.x + m1.x + bam, m0.y + m1.y + bam,
                           m0.z + m1.z + bam, m0.w + m1.w + bam};
            float ll[4] = {l0.x + l1.x + bal, l0.y + l1.y + bal,
                           l0.z + l1.z + bal, l0.w + l1.w + bal};
            float gs[4], uf[4], ug[4];
            #pragma unroll
            for (int q = 0; q < 4; ++q) {
                float m = fast_tanh(mm[q]);
                float sd = fast_softplus(san(ll[q]));
                float g = fast_tanh(san(m) + sd * nse[q]);
                float om = 1.f - kk[q] * kk[q];
                gs[q] = ff[q] + g;
                uf[q] = om * ff[q];
                ug[q] = om * g;
            }
            stchunk_f(go,  ewj * 2 + ewc, make_float4(gs[0], gs[1], gs[2], gs[3]));
            stchunk_f(ubf, ewj * 2 + ewc, make_float4(uf[0], uf[1], uf[2], uf[3]));
            stchunk_f(ubg, ewj * 2 + ewc, make_float4(ug[0], ug[1], ug[2], ug[3]));
        }
        __syncthreads();

        // ======== Stage F: jacf (128t) || jacg (128t), 4x4, 2 warp-uniform K-splits ========
        if (tid < 128) {
            int s = tid >> 6, u = tid & 63, h = u & 1, cg = u >> 1, j4 = 4 * cg;
            gaccum44(v, ubf, kw, ND, j4, h, s * 64, 64);
            store4(cb, s * 128 + j4, h, v);
        } else {
            int t = tid - 128, s = t >> 6, u = t & 63, h = u & 1, cg = u >> 1, j4 = 4 * cg;
            gaccum44(v, ubg, kw, ND, j4, h, s * 64, 64);
            store4(cb, 256 + s * 128 + j4, h, v);
        }
        __syncthreads();

        // ======== Stage F2: combine + reduce ========
        if (tid < 128) {
            float va[8], wa[8];
            load_row8(cb, tid, va); load_row8(cb, 128 + tid, wa);
            float sq[8];
            #pragma unroll
            for (int m = 0; m < 8; ++m) { float x = va[m] + wa[m]; sq[m] = x * x; }
            warp_reduce8(sq);
            if ((tid & 31) == 0) {
                int w = tid >> 5;
                #pragma unroll
                for (int m = 0; m < 8; ++m) redf[w * 8 + m] = sq[m];
            }
        } else {
            int col = tid - 128;
            float va[8], wa[8], kr[8];
            load_row8(cb, 256 + col, va); load_row8(cb, 384 + col, wa);
            load_row8(ko, col, kr);
            float sq[8];
            #pragma unroll
            for (int m = 0; m < 8; ++m) sq[m] = (va[m] + wa[m]) * kr[m];
            warp_reduce8(sq);
            if ((tid & 31) == 0) {
                int w = (tid - 128) >> 5;
                #pragma unroll
                for (int m = 0; m < 8; ++m) redg[w * 8 + m] = sq[m];
            }
        }
        __syncthreads();

        // ======== Update: inline mask + Euler + output ========
        {
            float sclq[4];
            #pragma unroll
            for (int q = 0; q < 4; ++q) {
                int m = 4 * ewc + q;
                float kn2 = kn2s[m];
                float jf2 = redf[m] + redf[8 + m] + redf[16 + m] + redf[24 + m];
                float c2v = redg[m] + redg[8 + m] + redg[16 + m] + redg[24 + m];
                float kn = sqrtf(kn2);
                float kn9 = kn2 * kn2 * kn2 * kn2 * kn;
                float c1 = sqrtf(jf2) - 60.0f * kn9;
                float c2 = c2v - 20.0f * kn9 * kn;
                bool mask = (c1 > 1e-8f) || (c2 < -1e-8f);
                sclq[q] = mask ? (0.5f * dt) : dt;
            }
            float4 xv = ldchunk_f(xs, ewj * 2 + ewc);
            float4 dv = ldchunk_f(go, ewj * 2 + ewc);
            float x[4] = {xv.x, xv.y, xv.z, xv.w};
            float d[4] = {dv.x, dv.y, dv.z, dv.w};
            float o[4];
            float* ob = out + (size_t)(step + 1) * BSZ * ND;
            #pragma unroll
            for (int q = 0; q < 4; ++q) {
                int m = 4 * ewc + q;
                o[q] = x[q] + d[q] * sclq[q];
                ob[(size_t)(r0 + m) * ND + ewj] = o[q];
            }
            stchunk_f(xs, ewj * 2 + ewc, make_float4(o[0], o[1], o[2], o[3]));
        }
        __syncthreads();
    }
}

extern "C" void kernel_launch(void* const* d_in, const int* in_sizes, int n_in,
                              void* d_out, int out_size) {
    (void)in_sizes; (void)n_in; (void)out_size;
    const float* y0   = (const float*)d_in[0];
    const float* tv   = (const float*)d_in[1];
    const float* nz   = (const float*)d_in[2];
    const float* fw1  = (const float*)d_in[3];
    const float* fb1  = (const float*)d_in[4];
    const float* fw2  = (const float*)d_in[5];
    const float* fb2  = (const float*)d_in[6];
    const float* fw3  = (const float*)d_in[7];
    const float* fb3  = (const float*)d_in[8];
    const float* amw1 = (const float*)d_in[9];
    const float* amb1 = (const float*)d_in[10];
    const float* amw2 = (const float*)d_in[11];
    const float* amb2 = (const float*)d_in[12];
    const float* amw3 = (const float*)d_in[13];
    const float* amb3 = (const float*)d_in[14];
    const float* alw1 = (const float*)d_in[15];
    const float* alb1 = (const float*)d_in[16];
    const float* alw2 = (const float*)d_in[17];
    const float* alb2 = (const float*)d_in[18];
    const float* alw3 = (const float*)d_in[19];
    const float* alb3 = (const float*)d_in[20];
    const float* kw   = (const float*)d_in[21];
    float* out = (float*)d_out;

    const int shmem = 20568 * sizeof(float);  // ~82.3 KB -> 2 blocks/SM
    cudaFuncSetAttribute(node_kernel, cudaFuncAttributeMaxDynamicSharedMemorySize, shmem);
    node_kernel<<<NBLOCKS, NTHR, shmem>>>(
        y0, tv, nz, fw1, fb1, fw2, fb2, fw3, fb3,
        amw1, amb1, amw2, amb2, amw3, amb3,
        alw1, alb1, alw2, alb2, alw3, alb3, kw, out);
}

// round 16
// speedup vs baseline: 1.0254x; 1.0254x over previous
#include <cuda_runtime.h>
#include <math.h>

#define BSZ 2048
#define ND 128
#define HID 256
#define SHD 64
#define NSTEPS 8
#define MROWS 8
#define NBLOCKS (BSZ / MROWS)
#define NTHR 256

typedef unsigned long long ull;

// ---------- packed f32x2 helpers ----------
__device__ __forceinline__ void fma2(ull &c, ull a, ull b) {
    asm("fma.rn.f32x2 %0, %1, %2, %3;" : "=l"(c) : "l"(a), "l"(b), "l"(c));
}
__device__ __forceinline__ ull packdup(float x) {
    ull r; asm("mov.b64 %0, {%1, %2};" : "=l"(r) : "f"(x), "f"(x)); return r;
}
__device__ __forceinline__ void unpack2(ull v, float &x, float &y) {
    asm("mov.b64 {%0, %1}, %2;" : "=f"(x), "=f"(y) : "l"(v));
}

// ---------- swizzled 16B-chunk shared layout ----------
// chunk ci = row*2 + half; physical slot = ci ^ ((ci>>3)&7)
#define CSW(ci) ((ci) ^ (((ci) >> 3) & 7))
__device__ __forceinline__ ulonglong2 ldphys_u(const float* buf, int pc) {
    return reinterpret_cast<const ulonglong2*>(buf)[pc];
}
__device__ __forceinline__ void stphys_f(float* buf, int pc, float4 v) {
    reinterpret_cast<float4*>(buf)[pc] = v;
}
__device__ __forceinline__ float4 ldchunk_f(const float* buf, int ci) {
    return reinterpret_cast<const float4*>(buf)[CSW(ci)];
}
__device__ __forceinline__ void stchunk_f(float* buf, int ci, float4 v) {
    reinterpret_cast<float4*>(buf)[CSW(ci)] = v;
}
__device__ __forceinline__ void load_row8(const float* buf, int r, float v[8]) {
    float4 c0 = ldchunk_f(buf, 2 * r);
    float4 c1 = ldchunk_f(buf, 2 * r + 1);
    v[0]=c0.x; v[1]=c0.y; v[2]=c0.z; v[3]=c0.w;
    v[4]=c1.x; v[5]=c1.y; v[6]=c1.z; v[7]=c1.w;
}
__device__ __forceinline__ void store_row8(float* buf, int r, const float v[8]) {
    stchunk_f(buf, 2 * r,     make_float4(v[0], v[1], v[2], v[3]));
    stchunk_f(buf, 2 * r + 1, make_float4(v[4], v[5], v[6], v[7]));
}

// ---------- fast transcendentals ----------
__device__ __forceinline__ float fast_tanh(float x) {
    float z = __expf(2.0f * x);
    return 1.0f - 2.0f / (z + 1.0f);
}
__device__ __forceinline__ float fast_softplus(float x) {
    float z = __expf(-fabsf(x));
    return fmaxf(x, 0.0f) + __logf(1.0f + z);
}
__device__ __forceinline__ float san(float x) { return isfinite(x) ? x : 0.f; }

// ---------- 4-col x 4-row accumulate (physical chunk index) ----------
__device__ __forceinline__ void acc44p(ull acc[8], const float* in_buf, int pc, float4 wv) {
    ulonglong2 p = ldphys_u(in_buf, pc);
    fma2(acc[0], p.x, packdup(wv.x)); fma2(acc[1], p.y, packdup(wv.x));
    fma2(acc[2], p.x, packdup(wv.y)); fma2(acc[3], p.y, packdup(wv.y));
    fma2(acc[4], p.x, packdup(wv.z)); fma2(acc[5], p.y, packdup(wv.z));
    fma2(acc[6], p.x, packdup(wv.w)); fma2(acc[7], p.y, packdup(wv.w));
}

// 4-col x 4-row GEMM partial; hoisted swizzle (k0 mult of 32, group of 4 stays in one 8-chunk block).
__device__ __forceinline__ void gaccum44(float v[16], const float* in_buf,
                                         const float* __restrict__ W, int ldw,
                                         int j4, int h, int k0, int KS) {
    ull acc[8];
    #pragma unroll
    for (int p = 0; p < 8; ++p) acc[p] = 0ULL;
    const int wld4 = ldw >> 2;
    const float4* __restrict__ wp = reinterpret_cast<const float4*>(W) + (size_t)k0 * wld4 + (j4 >> 2);
    float4 w[4];
    #pragma unroll
    for (int u = 0; u < 4; ++u) w[u] = wp[(size_t)u * wld4];
    wp += (size_t)4 * wld4;
    for (int kk = 0; kk < KS - 4; kk += 4) {
        float4 wn[4];
        #pragma unroll
        for (int u = 0; u < 4; ++u) wn[u] = wp[(size_t)u * wld4];
        wp += (size_t)4 * wld4;
        int ci0 = 2 * (k0 + kk) + h;           // = 8m + h
        int hi = ci0 & ~7, xo = (ci0 >> 3) & 7;
        #pragma unroll
        for (int u = 0; u < 4; ++u) acc44p(acc, in_buf, hi + ((h + 2 * u) ^ xo), w[u]);
        #pragma unroll
        for (int u = 0; u < 4; ++u) w[u] = wn[u];
    }
    {
        int ci0 = 2 * (k0 + KS - 4) + h;
        int hi = ci0 & ~7, xo = (ci0 >> 3) & 7;
        #pragma unroll
        for (int u = 0; u < 4; ++u) acc44p(acc, in_buf, hi + ((h + 2 * u) ^ xo), w[u]);
    }
    #pragma unroll
    for (int c = 0; c < 4; ++c) {
        unpack2(acc[2*c],     v[c*4+0], v[c*4+1]);
        unpack2(acc[2*c + 1], v[c*4+2], v[c*4+3]);
    }
}
// jbase mult of 4 -> 2*jbase+h = 8m+h; 4 chunks stay in one block
__device__ __forceinline__ void store4(float* buf, int jbase, int h, const float v[16]) {
    int ci0 = 2 * jbase + h;
    int hi = ci0 & ~7, xo = (ci0 >> 3) & 7;
    #pragma unroll
    for (int c = 0; c < 4; ++c)
        stphys_f(buf, hi + ((h + 2 * c) ^ xo),
                 make_float4(v[c*4+0], v[c*4+1], v[c*4+2], v[c*4+3]));
}

// ---------- 8-col x 4-row accumulate ----------
__device__ __forceinline__ void acc84p(ull acc[16], const float* in_buf, int pc,
                                       float4 wa, float4 wb) {
    ulonglong2 p = ldphys_u(in_buf, pc);
    fma2(acc[0],  p.x, packdup(wa.x)); fma2(acc[1],  p.y, packdup(wa.x));
    fma2(acc[2],  p.x, packdup(wa.y)); fma2(acc[3],  p.y, packdup(wa.y));
    fma2(acc[4],  p.x, packdup(wa.z)); fma2(acc[5],  p.y, packdup(wa.z));
    fma2(acc[6],  p.x, packdup(wa.w)); fma2(acc[7],  p.y, packdup(wa.w));
    fma2(acc[8],  p.x, packdup(wb.x)); fma2(acc[9],  p.y, packdup(wb.x));
    fma2(acc[10], p.x, packdup(wb.y)); fma2(acc[11], p.y, packdup(wb.y));
    fma2(acc[12], p.x, packdup(wb.z)); fma2(acc[13], p.y, packdup(wb.z));
    fma2(acc[14], p.x, packdup(wb.w)); fma2(acc[15], p.y, packdup(wb.w));
}

// 8-col x 4-row GEMM partial, depth-2 prefetch; hoisted swizzle (k0 even; pair stays in block).
__device__ __forceinline__ void gaccum84(float v[32], const float* in_buf,
                                         const float* __restrict__ W, int ldw,
                                         int j8, int h, int k0, int KS) {
    ull acc[16];
    #pragma unroll
    for (int p = 0; p < 16; ++p) acc[p] = 0ULL;
    const int wld4 = ldw >> 2;
    const float4* __restrict__ wp = reinterpret_cast<const float4*>(W) + (size_t)k0 * wld4 + (j8 >> 2);
    float4 wa[2], wb[2];
    #pragma unroll
    for (int u = 0; u < 2; ++u) { wa[u] = wp[(size_t)u * wld4]; wb[u] = wp[(size_t)u * wld4 + 1]; }
    wp += (size_t)2 * wld4;
    for (int kk = 0; kk < KS - 2; kk += 2) {
        float4 na[2], nb[2];
        #pragma unroll
        for (int u = 0; u < 2; ++u) { na[u] = wp[(size_t)u * wld4]; nb[u] = wp[(size_t)u * wld4 + 1]; }
        wp += (size_t)2 * wld4;
        int ci0 = 2 * (k0 + kk) + h;           // mult of 4 (+h): pair in one 8-block
        int hi = ci0 & ~7, lo = ci0 & 7, xo = (ci0 >> 3) & 7;
        #pragma unroll
        for (int u = 0; u < 2; ++u) acc84p(acc, in_buf, hi + ((lo + 2 * u) ^ xo), wa[u], wb[u]);
        #pragma unroll
        for (int u = 0; u < 2; ++u) { wa[u] = na[u]; wb[u] = nb[u]; }
    }
    {
        int ci0 = 2 * (k0 + KS - 2) + h;
        int hi = ci0 & ~7, lo = ci0 & 7, xo = (ci0 >> 3) & 7;
        #pragma unroll
        for (int u = 0; u < 2; ++u) acc84p(acc, in_buf, hi + ((lo + 2 * u) ^ xo), wa[u], wb[u]);
    }
    #pragma unroll
    for (int c = 0; c < 8; ++c) {
        unpack2(acc[2*c],     v[c*4+0], v[c*4+1]);
        unpack2(acc[2*c + 1], v[c*4+2], v[c*4+3]);
    }
}
// jbase mult of 8 -> two aligned half-groups
__device__ __forceinline__ void store8(float* buf, int jbase, int h, const float v[32]) {
    int ci0 = 2 * jbase + h;                   // = 16m + h
    int hi = ci0 & ~7, xo = (ci0 >> 3) & 7;
    int hi2 = hi + 8, xo2 = ((ci0 + 8) >> 3) & 7;
    #pragma unroll
    for (int c = 0; c < 4; ++c)
        stphys_f(buf, hi + ((h + 2 * c) ^ xo),
                 make_float4(v[c*4+0], v[c*4+1], v[c*4+2], v[c*4+3]));
    #pragma unroll
    for (int c = 0; c < 4; ++c)
        stphys_f(buf, hi2 + ((h + 2 * c) ^ xo2),
                 make_float4(v[(c+4)*4+0], v[(c+4)*4+1], v[(c+4)*4+2], v[(c+4)*4+3]));
}

__device__ __forceinline__ void warp_reduce8(float sq[8]) {
    #pragma unroll
    for (int off = 16; off > 0; off >>= 1) {
        #pragma unroll
        for (int m = 0; m < 8; ++m)
            sq[m] += __shfl_down_sync(0xffffffffu, sq[m], off);
    }
}

__global__ void __launch_bounds__(NTHR, 2)
node_kernel(const float* __restrict__ y0, const float* __restrict__ tv,
            const float* __restrict__ noise,
            const float* __restrict__ fw1, const float* __restrict__ fb1,
            const float* __restrict__ fw2, const float* __restrict__ fb2,
            const float* __restrict__ fw3, const float* __restrict__ fb3,
            const float* __restrict__ amw1, const float* __restrict__ amb1,
            const float* __restrict__ amw2, const float* __restrict__ amb2,
            const float* __restrict__ amw3, const float* __restrict__ amb3,
            const float* __restrict__ alw1, const float* __restrict__ alb1,
            const float* __restrict__ alw2, const float* __restrict__ alb2,
            const float* __restrict__ alw3, const float* __restrict__ alb3,
            const float* __restrict__ kw, float* __restrict__ out)
{
    extern __shared__ float smem[];
    float* xs   = smem;              // 1024  [128][8]
    float* h1   = xs + 1024;         // 2048  [256][8]
    float* h2   = h1 + 2048;         // 2048
    float* fo   = h2 + 2048;         // 1024
    float* ko   = fo + 1024;         // 1024
    float* go   = ko + 1024;         // 1024  (f+g)
    float* ubf  = go + 1024;         // 1024
    float* ubg  = ubf + 1024;        // 1024
    float* a1m  = ubg + 1024;        // 512   [64][8]
    float* a1l  = a1m + 512;         // 512
    float* a2m  = a1l + 512;         // 512
    float* a2l  = a2m + 512;         // 512
    float* cb   = a2l + 512;         // 8192  partial scratch [1024][8]
    float* redk = cb + 8192;         // 16
    float* redf = redk + 16;         // 32
    float* redg = redf + 32;         // 32
    float* kn2s = redg + 32;         // 8

    const int tid = threadIdx.x;
    const int r0 = blockIdx.x * MROWS;
    const float dt = tv[1] - tv[0];
    const int ewj = tid & 127;       // elementwise: col j
    const int ewc = tid >> 7;        // elementwise: half (rows 4c..4c+3)

    // load y0 tile (transposed [128][8], swizzled); emit output step 0
    {
        float a[4];
        #pragma unroll
        for (int q = 0; q < 4; ++q) {
            int m = 4 * ewc + q;
            float val = y0[(size_t)(r0 + m) * ND + ewj];
            out[(size_t)(r0 + m) * ND + ewj] = val;
            a[q] = val;
        }
        stchunk_f(xs, ewj * 2 + ewc, make_float4(a[0], a[1], a[2], a[3]));
    }
    __syncthreads();

    for (int step = 0; step < NSTEPS; ++step) {
        float v[16];
        float nse[4];
        {
            const float* np = noise + (size_t)step * BSZ * ND + (size_t)(r0 + 4 * ewc) * ND + ewj;
            #pragma unroll
            for (int q = 0; q < 4; ++q) nse[q] = np[(size_t)q * ND];
        }

        // ======== Stage A: f1(128t) || k(64t) || am1(32t) || al1(32t), 4x4, full K ========
        if (tid < 128) {
            int h = tid & 1, cg = tid >> 1, j4 = 4 * cg;
            gaccum44(v, xs, fw1, HID, j4, h, 0, ND);
            float4 b = reinterpret_cast<const float4*>(fb1)[cg];
            float bb[4] = {b.x, b.y, b.z, b.w};
            #pragma unroll
            for (int c = 0; c < 4; ++c)
                #pragma unroll
                for (int q = 0; q < 4; ++q) v[c*4+q] = fast_tanh(v[c*4+q] + bb[c]);
            store4(h1, j4, h, v);
        } else if (tid < 192) {
            int u = tid - 128, h = u & 1, cg = u >> 1, j4 = 4 * cg;
            gaccum44(v, xs, kw, ND, j4, h, 0, ND);
            float sq4[4] = {0.f, 0.f, 0.f, 0.f};
            #pragma unroll
            for (int c = 0; c < 4; ++c)
                #pragma unroll
                for (int q = 0; q < 4; ++q) {
                    float t = fast_tanh(v[c*4+q]);
                    v[c*4+q] = t;
                    sq4[q] += t * t;
                }
            store4(ko, j4, h, v);
            #pragma unroll
            for (int off = 16; off >= 2; off >>= 1)
                #pragma unroll
                for (int q = 0; q < 4; ++q)
                    sq4[q] += __shfl_down_sync(0xffffffffu, sq4[q], off);
            if ((tid & 31) < 2) {
                int w = (tid - 128) >> 5;
                int hh = tid & 1;
                #pragma unroll
                for (int q = 0; q < 4; ++q) redk[w * 8 + hh * 4 + q] = sq4[q];
            }
        } else if (tid < 224) {
            int u = tid - 192, h = u & 1, cg = u >> 1, j4 = 4 * cg;
            gaccum44(v, xs, amw1, SHD, j4, h, 0, ND);
            float4 b = reinterpret_cast<const float4*>(amb1)[cg];
            float bb[4] = {b.x, b.y, b.z, b.w};
            #pragma unroll
            for (int c = 0; c < 4; ++c)
                #pragma unroll
                for (int q = 0; q < 4; ++q) v[c*4+q] = fmaxf(v[c*4+q] + bb[c], 0.f);
            store4(a1m, j4, h, v);
        } else {
            int u = tid - 224, h = u & 1, cg = u >> 1, j4 = 4 * cg;
            gaccum44(v, xs, alw1, SHD, j4, h, 0, ND);
            float4 b = reinterpret_cast<const float4*>(alb1)[cg];
            float bb[4] = {b.x, b.y, b.z, b.w};
            #pragma unroll
            for (int c = 0; c < 4; ++c)
                #pragma unroll
                for (int q = 0; q < 4; ++q) v[c*4+q] = fmaxf(v[c*4+q] + bb[c], 0.f);
            store4(a1l, j4, h, v);
        }
        __syncthreads();

        // ======== Stage B: f2, 8col x 4row, 4 warp-uniform K-splits; ALL partials to cb ========
        {
            int s = tid >> 6, u = tid & 63, h = u & 1, cg = u >> 1, j8 = 8 * cg;
            float v32[32];
            gaccum84(v32, h1, fw2, HID, j8, h, s * 64, 64);
            store8(cb, s * 256 + j8, h, v32);
        }
        __syncthreads();

        // ======== Stage B2: h2 combine (256t, 1 col each) + finish ||k||^2 ========
        {
            float acc8[8] = {0,0,0,0,0,0,0,0};
            #pragma unroll
            for (int s = 0; s < 4; ++s) {
                float t8[8];
                load_row8(cb, s * 256 + tid, t8);
                #pragma unroll
                for (int m = 0; m < 8; ++m) acc8[m] += t8[m];
            }
            float b = fb2[tid];
            #pragma unroll
            for (int m = 0; m < 8; ++m) acc8[m] = fast_softplus(acc8[m] + b);
            store_row8(h2, tid, acc8);
            if (tid < 8) kn2s[tid] = redk[tid] + redk[8 + tid];
        }
        __syncthreads();

        // ======== Stage C1: f3, 4x4, 4 warp-uniform K-splits; ALL partials to cb ========
        {
            int s = tid >> 6, u = tid & 63, h = u & 1, cg = u >> 1, j4 = 4 * cg;
            gaccum44(v, h2, fw3, ND, j4, h, s * 64, 64);
            store4(cb, s * 128 + j4, h, v);
        }
        __syncthreads();

        // ======== Stage C2: f3 combine (128t) || am2 (32t, 4x4) || al2 (32t, 4x4) ========
        if (tid < 128) {
            float r8[8] = {0,0,0,0,0,0,0,0};
            #pragma unroll
            for (int s = 0; s < 4; ++s) {
                float4 c0 = ldchunk_f(cb, (s * 128 + tid) * 2);
                float4 c1 = ldchunk_f(cb, (s * 128 + tid) * 2 + 1);
                r8[0]+=c0.x; r8[1]+=c0.y; r8[2]+=c0.z; r8[3]+=c0.w;
                r8[4]+=c1.x; r8[5]+=c1.y; r8[6]+=c1.z; r8[7]+=c1.w;
            }
            float b = fb3[tid];
            #pragma unroll
            for (int m = 0; m < 8; ++m) r8[m] += b;
            store_row8(fo, tid, r8);
        } else if (tid < 160) {
            int u = tid - 128, h = u & 1, cg = u >> 1, j4 = 4 * cg;
            gaccum44(v, a1m, amw2, SHD, j4, h, 0, SHD);
            float4 b = reinterpret_cast<const float4*>(amb2)[cg];
            float bb[4] = {b.x, b.y, b.z, b.w};
            #pragma unroll
            for (int c = 0; c < 4; ++c)
                #pragma unroll
                for (int q = 0; q < 4; ++q) v[c*4+q] = fmaxf(v[c*4+q] + bb[c], 0.f);
            store4(a2m, j4, h, v);
        } else if (tid < 192) {
            int u = tid - 160, h = u & 1, cg = u >> 1, j4 = 4 * cg;
            gaccum44(v, a1l, alw2, SHD, j4, h, 0, SHD);
            float4 b = reinterpret_cast<const float4*>(alb2)[cg];
            float bb[4] = {b.x, b.y, b.z, b.w};
            #pragma unroll
            for (int c = 0; c < 4; ++c)
                #pragma unroll
                for (int q = 0; q < 4; ++q) v[c*4+q] = fmaxf(v[c*4+q] + bb[c], 0.f);
            store4(a2l, j4, h, v);
        }
        __syncthreads();

        // ======== Stage C3: am3 (128t, 4x4, Ksplit2) || al3 (128t, 4x4, Ksplit2); partials to cb ========
        if (tid < 128) {
            int s = tid >> 6, u = tid & 63, h = u & 1, cg = u >> 1, j4 = 4 * cg;
            gaccum44(v, a2m, amw3, ND, j4, h, s * 32, 32);
            store4(cb, s * 128 + j4, h, v);
        } else {
            int t = tid - 128, s = t >> 6, u = t & 63, h = u & 1, cg = u >> 1, j4 = 4 * cg;
            gaccum44(v, a2l, alw3, ND, j4, h, s * 32, 32);
            store4(cb, 256 + s * 128 + j4, h, v);
        }
        __syncthreads();

        // ======== Stage E: combine am3/al3, g, f+g, u_f, u_g ========
        {
            float4 kv = ldchunk_f(ko,  ewj * 2 + ewc);
            float4 fv = ldchunk_f(fo,  ewj * 2 + ewc);
            float4 m0 = ldchunk_f(cb, ewj * 2 + ewc);
            float4 m1 = ldchunk_f(cb, (128 + ewj) * 2 + ewc);
            float4 l0 = ldchunk_f(cb, (256 + ewj) * 2 + ewc);
            float4 l1 = ldchunk_f(cb, (384 + ewj) * 2 + ewc);
            float bam = amb3[ewj], bal = alb3[ewj];
            float kk[4] = {kv.x, kv.y, kv.z, kv.w};
            float ff[4] = {fv.x, fv.y, fv.z, fv.w};
            float mm[4] = {m0.x + m1.x + bam, m0.y + m1.y + bam,
                           m0.z + m1.z + bam, m0.w + m1.w + bam};
            float ll[4] = {l0.x + l1.x + bal, l0.y + l1.y + bal,
                           l0.z + l1.z + bal, l0.w + l1.w + bal};
            float gs[4], uf[4], ug[4];
            #pragma unroll
            for (int q = 0; q < 4; ++q) {
                float m = fast_tanh(mm[q]);
                float sd = fast_softplus(san(ll[q]));
                float g = fast_tanh(san(m) + sd * nse[q]);
                float om = 1.f - kk[q] * kk[q];
                gs[q] = ff[q] + g;
                uf[q] = om * ff[q];
                ug[q] = om * g;
            }
            stchunk_f(go,  ewj * 2 + ewc, make_float4(gs[0], gs[1], gs[2], gs[3]));
            stchunk_f(ubf, ewj * 2 + ewc, make_float4(uf[0], uf[1], uf[2], uf[3]));
            stchunk_f(ubg, ewj * 2 + ewc, make_float4(ug[0], ug[1], ug[2], ug[3]));
        }
        __syncthreads();

        // ======== Stage F: jacf (128t) || jacg (128t), 4x4, 2 warp-uniform K-splits ========
        if (tid < 128) {
            int s = tid >> 6, u = tid & 63, h = u & 1, cg = u >> 1, j4 = 4 * cg;
            gaccum44(v, ubf, kw, ND, j4, h, s * 64, 64);
            store4(cb, s * 128 + j4, h, v);
        } else {
            int t = tid - 128, s = t >> 6, u = t & 63, h = u & 1, cg = u >> 1, j4 = 4 * cg;
            gaccum44(v, ubg, kw, ND, j4, h, s * 64, 64);
            store4(cb, 256 + s * 128 + j4, h, v);
        }
        __syncthreads();

        // ======== Stage F2: combine + reduce ========
        if (tid < 128) {
            float va[8], wa[8];
            load_row8(cb, tid, va); load_row8(cb, 128 + tid, wa);
            float sq[8];
            #pragma unroll
            for (int m = 0; m < 8; ++m) { float x = va[m] + wa[m]; sq[m] = x * x; }
            warp_reduce8(sq);
            if ((tid & 31) == 0) {
                int w = tid >> 5;
                #pragma unroll
                for (int m = 0; m < 8; ++m) redf[w * 8 + m] = sq[m];
            }
        } else {
            int col = tid - 128;
            float va[8], wa[8], kr[8];
            load_row8(cb, 256 + col, va); load_row8(cb, 384 + col, wa);
            load_row8(ko, col, kr);
            float sq[8];
            #pragma unroll
            for (int m = 0; m < 8; ++m) sq[m] = (va[m] + wa[m]) * kr[m];
            warp_reduce8(sq);
            if ((tid & 31) == 0) {
                int w = (tid - 128) >> 5;
                #pragma unroll
                for (int m = 0; m < 8; ++m) redg[w * 8 + m] = sq[m];
            }
        }
        __syncthreads();

        // ======== Update: inline mask + Euler + output ========
        {
            float sclq[4];
            #pragma unroll
            for (int q = 0; q < 4; ++q) {
                int m = 4 * ewc + q;
                float kn2 = kn2s[m];
                float jf2 = redf[m] + redf[8 + m] + redf[16 + m] + redf[24 + m];
                float c2v = redg[m] + redg[8 + m] + redg[16 + m] + redg[24 + m];
                float kn = sqrtf(kn2);
                float kn9 = kn2 * kn2 * kn2 * kn2 * kn;
                float c1 = sqrtf(jf2) - 60.0f * kn9;
                float c2 = c2v - 20.0f * kn9 * kn;
                bool mask = (c1 > 1e-8f) || (c2 < -1e-8f);
                sclq[q] = mask ? (0.5f * dt) : dt;
            }
            float4 xv = ldchunk_f(xs, ewj * 2 + ewc);
            float4 dv = ldchunk_f(go, ewj * 2 + ewc);
            float x[4] = {xv.x, xv.y, xv.z, xv.w};
            float d[4] = {dv.x, dv.y, dv.z, dv.w};
            float o[4];
            float* ob = out + (size_t)(step + 1) * BSZ * ND;
            #pragma unroll
            for (int q = 0; q < 4; ++q) {
                int m = 4 * ewc + q;
                o[q] = x[q] + d[q] * sclq[q];
                ob[(size_t)(r0 + m) * ND + ewj] = o[q];
            }
            stchunk_f(xs, ewj * 2 + ewc, make_float4(o[0], o[1], o[2], o[3]));
        }
        __syncthreads();
    }
}

extern "C" void kernel_launch(void* const* d_in, const int* in_sizes, int n_in,
                              void* d_out, int out_size) {
    (void)in_sizes; (void)n_in; (void)out_size;
    const float* y0   = (const float*)d_in[0];
    const float* tv   = (const float*)d_in[1];
    const float* nz   = (const float*)d_in[2];
    const float* fw1  = (const float*)d_in[3];
    const float* fb1  = (const float*)d_in[4];
    const float* fw2  = (const float*)d_in[5];
    const float* fb2  = (const float*)d_in[6];
    const float* fw3  = (const float*)d_in[7];
    const float* fb3  = (const float*)d_in[8];
    const float* amw1 = (const float*)d_in[9];
    const float* amb1 = (const float*)d_in[10];
    const float* amw2 = (const float*)d_in[11];
    const float* amb2 = (const float*)d_in[12];
    const float* amw3 = (const float*)d_in[13];
    const float* amb3 = (const float*)d_in[14];
    const float* alw1 = (const float*)d_in[15];
    const float* alb1 = (const float*)d_in[16];
    const float* alw2 = (const float*)d_in[17];
    const float* alb2 = (const float*)d_in[18];
    const float* alw3 = (const float*)d_in[19];
    const float* alb3 = (const float*)d_in[20];
    const float* kw   = (const float*)d_in[21];
    float* out = (float*)d_out;

    const int shmem = 20568 * sizeof(float);  // ~82.3 KB -> 2 blocks/SM
    cudaFuncSetAttribute(node_kernel, cudaFuncAttributeMaxDynamicSharedMemorySize, shmem);
    node_kernel<<<NBLOCKS, NTHR, shmem>>>(
        y0, tv, nz, fw1, fb1, fw2, fb2, fw3, fb3,
        amw1, amb1, amw2, amb2, amw3, amb3,
        alw1, alb1, alw2, alb2, alw3, alb3, kw, out);
}

// round 17
// speedup vs baseline: 1.0500x; 1.0240x over previous
#include <cuda_runtime.h>
#include <math.h>

#define BSZ 2048
#define ND 128
#define HID 256
#define SHD 64
#define NSTEPS 8
#define MROWS 8
#define NBLOCKS (BSZ / MROWS)
#define NTHR 256

typedef unsigned long long ull;

// ---------- packed f32x2 helpers ----------
__device__ __forceinline__ void fma2(ull &c, ull a, ull b) {
    asm("fma.rn.f32x2 %0, %1, %2, %3;" : "=l"(c) : "l"(a), "l"(b), "l"(c));
}
__device__ __forceinline__ ull packdup(float x) {
    ull r; asm("mov.b64 %0, {%1, %2};" : "=l"(r) : "f"(x), "f"(x)); return r;
}
__device__ __forceinline__ void unpack2(ull v, float &x, float &y) {
    asm("mov.b64 {%0, %1}, %2;" : "=f"(x), "=f"(y) : "l"(v));
}

// ---------- swizzled 16B-chunk shared layout ----------
// Buffer = [rows][8 floats]; chunk ci = row*2 + half. Physical slot = ci ^ ((ci>>3)&7).
#define CSW(ci) ((ci) ^ (((ci) >> 3) & 7))
__device__ __forceinline__ ulonglong2 ldchunk_u(const float* buf, int ci) {
    return reinterpret_cast<const ulonglong2*>(buf)[CSW(ci)];
}
__device__ __forceinline__ float4 ldchunk_f(const float* buf, int ci) {
    return reinterpret_cast<const float4*>(buf)[CSW(ci)];
}
__device__ __forceinline__ void stchunk_f(float* buf, int ci, float4 v) {
    reinterpret_cast<float4*>(buf)[CSW(ci)] = v;
}
__device__ __forceinline__ void load_row8(const float* buf, int r, float v[8]) {
    float4 c0 = ldchunk_f(buf, 2 * r);
    float4 c1 = ldchunk_f(buf, 2 * r + 1);
    v[0]=c0.x; v[1]=c0.y; v[2]=c0.z; v[3]=c0.w;
    v[4]=c1.x; v[5]=c1.y; v[6]=c1.z; v[7]=c1.w;
}
__device__ __forceinline__ void store_row8(float* buf, int r, const float v[8]) {
    stchunk_f(buf, 2 * r,     make_float4(v[0], v[1], v[2], v[3]));
    stchunk_f(buf, 2 * r + 1, make_float4(v[4], v[5], v[6], v[7]));
}

// ---------- fast transcendentals ----------
__device__ __forceinline__ float fast_tanh(float x) {
    float z = __expf(2.0f * x);
    return 1.0f - 2.0f / (z + 1.0f);
}
__device__ __forceinline__ float fast_softplus(float x) {
    float z = __expf(-fabsf(x));
    return fmaxf(x, 0.0f) + __logf(1.0f + z);
}
__device__ __forceinline__ float san(float x) { return isfinite(x) ? x : 0.f; }

// ---------- 4-col x 4-row accumulate ----------
__device__ __forceinline__ void acc44(ull acc[8], const float* in_buf, int k, int h, float4 wv) {
    ulonglong2 p = ldchunk_u(in_buf, 2 * k + h);
    fma2(acc[0], p.x, packdup(wv.x)); fma2(acc[1], p.y, packdup(wv.x));
    fma2(acc[2], p.x, packdup(wv.y)); fma2(acc[3], p.y, packdup(wv.y));
    fma2(acc[4], p.x, packdup(wv.z)); fma2(acc[5], p.y, packdup(wv.z));
    fma2(acc[6], p.x, packdup(wv.w)); fma2(acc[7], p.y, packdup(wv.w));
}

// 4-col x 4-row GEMM partial. v[c*4+q] = (col j4+c, row 4h+q). KS mult of 4, >= 8.
__device__ __forceinline__ void gaccum44(float v[16], const float* in_buf,
                                         const float* __restrict__ W, int ldw,
                                         int j4, int h, int k0, int KS) {
    ull acc[8];
    #pragma unroll
    for (int p = 0; p < 8; ++p) acc[p] = 0ULL;
    const int wld4 = ldw >> 2;
    const float4* __restrict__ wp = reinterpret_cast<const float4*>(W) + (size_t)k0 * wld4 + (j4 >> 2);
    float4 w[4];
    #pragma unroll
    for (int u = 0; u < 4; ++u) w[u] = wp[(size_t)u * wld4];
    wp += (size_t)4 * wld4;
    for (int kk = 0; kk < KS - 4; kk += 4) {
        float4 wn[4];
        #pragma unroll
        for (int u = 0; u < 4; ++u) wn[u] = wp[(size_t)u * wld4];
        wp += (size_t)4 * wld4;
        #pragma unroll
        for (int u = 0; u < 4; ++u) acc44(acc, in_buf, k0 + kk + u, h, w[u]);
        #pragma unroll
        for (int u = 0; u < 4; ++u) w[u] = wn[u];
    }
    #pragma unroll
    for (int u = 0; u < 4; ++u) acc44(acc, in_buf, k0 + KS - 4 + u, h, w[u]);
    #pragma unroll
    for (int c = 0; c < 4; ++c) {
        unpack2(acc[2*c],     v[c*4+0], v[c*4+1]);
        unpack2(acc[2*c + 1], v[c*4+2], v[c*4+3]);
    }
}
__device__ __forceinline__ void store4(float* buf, int jbase, int h, const float v[16]) {
    #pragma unroll
    for (int c = 0; c < 4; ++c)
        stchunk_f(buf, (jbase + c) * 2 + h, make_float4(v[c*4+0], v[c*4+1], v[c*4+2], v[c*4+3]));
}

// ---------- 8-col x 4-row accumulate (one 16B LDS feeds 16 fma2) ----------
__device__ __forceinline__ void acc84(ull acc[16], const float* in_buf, int k, int h,
                                      float4 wa, float4 wb) {
    ulonglong2 p = ldchunk_u(in_buf, 2 * k + h);
    fma2(acc[0],  p.x, packdup(wa.x)); fma2(acc[1],  p.y, packdup(wa.x));
    fma2(acc[2],  p.x, packdup(wa.y)); fma2(acc[3],  p.y, packdup(wa.y));
    fma2(acc[4],  p.x, packdup(wa.z)); fma2(acc[5],  p.y, packdup(wa.z));
    fma2(acc[6],  p.x, packdup(wa.w)); fma2(acc[7],  p.y, packdup(wa.w));
    fma2(acc[8],  p.x, packdup(wb.x)); fma2(acc[9],  p.y, packdup(wb.x));
    fma2(acc[10], p.x, packdup(wb.y)); fma2(acc[11], p.y, packdup(wb.y));
    fma2(acc[12], p.x, packdup(wb.z)); fma2(acc[13], p.y, packdup(wb.z));
    fma2(acc[14], p.x, packdup(wb.w)); fma2(acc[15], p.y, packdup(wb.w));
}

// 8-col x 4-row GEMM partial, depth-2 prefetch. v[c*4+q], c=0..7. KS mult of 2, >= 4.
__device__ __forceinline__ void gaccum84(float v[32], const float* in_buf,
                                         const float* __restrict__ W, int ldw,
                                         int j8, int h, int k0, int KS) {
    ull acc[16];
    #pragma unroll
    for (int p = 0; p < 16; ++p) acc[p] = 0ULL;
    const int wld4 = ldw >> 2;
    const float4* __restrict__ wp = reinterpret_cast<const float4*>(W) + (size_t)k0 * wld4 + (j8 >> 2);
    float4 wa[2], wb[2];
    #pragma unroll
    for (int u = 0; u < 2; ++u) { wa[u] = wp[(size_t)u * wld4]; wb[u] = wp[(size_t)u * wld4 + 1]; }
    wp += (size_t)2 * wld4;
    for (int kk = 0; kk < KS - 2; kk += 2) {
        float4 na[2], nb[2];
        #pragma unroll
        for (int u = 0; u < 2; ++u) { na[u] = wp[(size_t)u * wld4]; nb[u] = wp[(size_t)u * wld4 + 1]; }
        wp += (size_t)2 * wld4;
        #pragma unroll
        for (int u = 0; u < 2; ++u) acc84(acc, in_buf, k0 + kk + u, h, wa[u], wb[u]);
        #pragma unroll
        for (int u = 0; u < 2; ++u) { wa[u] = na[u]; wb[u] = nb[u]; }
    }
    #pragma unroll
    for (int u = 0; u < 2; ++u) acc84(acc, in_buf, k0 + KS - 2 + u, h, wa[u], wb[u]);
    #pragma unroll
    for (int c = 0; c < 8; ++c) {
        unpack2(acc[2*c],     v[c*4+0], v[c*4+1]);
        unpack2(acc[2*c + 1], v[c*4+2], v[c*4+3]);
    }
}
__device__ __forceinline__ void store8(float* buf, int jbase, int h, const float v[32]) {
    #pragma unroll
    for (int c = 0; c < 8; ++c)
        stchunk_f(buf, (jbase + c) * 2 + h, make_float4(v[c*4+0], v[c*4+1], v[c*4+2], v[c*4+3]));
}

__device__ __forceinline__ void warp_reduce8(float sq[8]) {
    #pragma unroll
    for (int off = 16; off > 0; off >>= 1) {
        #pragma unroll
        for (int m = 0; m < 8; ++m)
            sq[m] += __shfl_down_sync(0xffffffffu, sq[m], off);
    }
}

__global__ void __launch_bounds__(NTHR, 2)
node_kernel(const float* __restrict__ y0, const float* __restrict__ tv,
            const float* __restrict__ noise,
            const float* __restrict__ fw1, const float* __restrict__ fb1,
            const float* __restrict__ fw2, const float* __restrict__ fb2,
            const float* __restrict__ fw3, const float* __restrict__ fb3,
            const float* __restrict__ amw1, const float* __restrict__ amb1,
            const float* __restrict__ amw2, const float* __restrict__ amb2,
            const float* __restrict__ amw3, const float* __restrict__ amb3,
            const float* __restrict__ alw1, const float* __restrict__ alb1,
            const float* __restrict__ alw2, const float* __restrict__ alb2,
            const float* __restrict__ alw3, const float* __restrict__ alb3,
            const float* __restrict__ kw, float* __restrict__ out)
{
    extern __shared__ float smem[];
    float* xs   = smem;              // 1024  [128][8]
    float* h1   = xs + 1024;         // 2048  [256][8]
    float* h2   = h1 + 2048;         // 2048
    float* fo   = h2 + 2048;         // 1024
    float* ko   = fo + 1024;         // 1024
    float* go   = ko + 1024;         // 1024  (f+g)
    float* ubf  = go + 1024;         // 1024
    float* ubg  = ubf + 1024;        // 1024
    float* a1m  = ubg + 1024;        // 512   [64][8]
    float* a1l  = a1m + 512;         // 512
    float* a2m  = a1l + 512;         // 512
    float* a2l  = a2m + 512;         // 512
    float* cb   = a2l + 512;         // 8192  partial scratch [1024][8]
    float* redk = cb + 8192;         // 16
    float* redf = redk + 16;         // 32
    float* redg = redf + 32;         // 32
    float* kn2s = redg + 32;         // 8

    const int tid = threadIdx.x;
    const int r0 = blockIdx.x * MROWS;
    const float dt = tv[1] - tv[0];
    const int ewj = tid & 127;
    const int ewc = tid >> 7;

    // load y0 tile (transposed [128][8], swizzled); emit output step 0
    {
        float a[4];
        #pragma unroll
        for (int q = 0; q < 4; ++q) {
            int m = 4 * ewc + q;
            float val = y0[(size_t)(r0 + m) * ND + ewj];
            out[(size_t)(r0 + m) * ND + ewj] = val;
            a[q] = val;
        }
        stchunk_f(xs, ewj * 2 + ewc, make_float4(a[0], a[1], a[2], a[3]));
    }
    __syncthreads();

    for (int step = 0; step < NSTEPS; ++step) {
        float v[16];
        float nse[4];
        {
            const float* np = noise + (size_t)step * BSZ * ND + (size_t)(r0 + 4 * ewc) * ND + ewj;
            #pragma unroll
            for (int q = 0; q < 4; ++q) nse[q] = np[(size_t)q * ND];
        }

        // ======== Stage A: f1(128t) || k(64t) || am1(32t) || al1(32t), 4x4, full K ========
        if (tid < 128) {
            int h = tid & 1, cg = tid >> 1, j4 = 4 * cg;
            gaccum44(v, xs, fw1, HID, j4, h, 0, ND);
            float4 b = reinterpret_cast<const float4*>(fb1)[cg];
            float bb[4] = {b.x, b.y, b.z, b.w};
            #pragma unroll
            for (int c = 0; c < 4; ++c)
                #pragma unroll
                for (int q = 0; q < 4; ++q) v[c*4+q] = fast_tanh(v[c*4+q] + bb[c]);
            store4(h1, j4, h, v);
        } else if (tid < 192) {
            int u = tid - 128, h = u & 1, cg = u >> 1, j4 = 4 * cg;
            gaccum44(v, xs, kw, ND, j4, h, 0, ND);
            float sq4[4] = {0.f, 0.f, 0.f, 0.f};
            #pragma unroll
            for (int c = 0; c < 4; ++c)
                #pragma unroll
                for (int q = 0; q < 4; ++q) {
                    float t = fast_tanh(v[c*4+q]);
                    v[c*4+q] = t;
                    sq4[q] += t * t;
                }
            store4(ko, j4, h, v);
            #pragma unroll
            for (int off = 16; off >= 2; off >>= 1)
                #pragma unroll
                for (int q = 0; q < 4; ++q)
                    sq4[q] += __shfl_down_sync(0xffffffffu, sq4[q], off);
            if ((tid & 31) < 2) {
                int w = (tid - 128) >> 5;
                int hh = tid & 1;
                #pragma unroll
                for (int q = 0; q < 4; ++q) redk[w * 8 + hh * 4 + q] = sq4[q];
            }
        } else if (tid < 224) {
            int u = tid - 192, h = u & 1, cg = u >> 1, j4 = 4 * cg;
            gaccum44(v, xs, amw1, SHD, j4, h, 0, ND);
            float4 b = reinterpret_cast<const float4*>(amb1)[cg];
            float bb[4] = {b.x, b.y, b.z, b.w};
            #pragma unroll
            for (int c = 0; c < 4; ++c)
                #pragma unroll
                for (int q = 0; q < 4; ++q) v[c*4+q] = fmaxf(v[c*4+q] + bb[c], 0.f);
            store4(a1m, j4, h, v);
        } else {
            int u = tid - 224, h = u & 1, cg = u >> 1, j4 = 4 * cg;
            gaccum44(v, xs, alw1, SHD, j4, h, 0, ND);
            float4 b = reinterpret_cast<const float4*>(alb1)[cg];
            float bb[4] = {b.x, b.y, b.z, b.w};
            #pragma unroll
            for (int c = 0; c < 4; ++c)
                #pragma unroll
                for (int q = 0; q < 4; ++q) v[c*4+q] = fmaxf(v[c*4+q] + bb[c], 0.f);
            store4(a1l, j4, h, v);
        }
        __syncthreads();

        // ======== Stage B: f2, 8col x 4row, 4 warp-uniform K-splits; ALL partials to cb ========
        {
            int s = tid >> 6, u = tid & 63, h = u & 1, cg = u >> 1, j8 = 8 * cg;
            float v32[32];
            gaccum84(v32, h1, fw2, HID, j8, h, s * 64, 64);
            store8(cb, s * 256 + j8, h, v32);
        }
        __syncthreads();

        // ======== Stage B2: h2 combine (256t, 1 col each) + finish ||k||^2 ========
        {
            float acc8[8] = {0,0,0,0,0,0,0,0};
            #pragma unroll
            for (int s = 0; s < 4; ++s) {
                float t8[8];
                load_row8(cb, s * 256 + tid, t8);
                #pragma unroll
                for (int m = 0; m < 8; ++m) acc8[m] += t8[m];
            }
            float b = fb2[tid];
            #pragma unroll
            for (int m = 0; m < 8; ++m) acc8[m] = fast_softplus(acc8[m] + b);
            store_row8(h2, tid, acc8);
            if (tid < 8) kn2s[tid] = redk[tid] + redk[8 + tid];
        }
        __syncthreads();

        // ======== Stage C1: f3, 4x4, 4 warp-uniform K-splits; ALL partials to cb ========
        {
            int s = tid >> 6, u = tid & 63, h = u & 1, cg = u >> 1, j4 = 4 * cg;
            gaccum44(v, h2, fw3, ND, j4, h, s * 64, 64);
            store4(cb, s * 128 + j4, h, v);
        }
        __syncthreads();

        // ======== Stage C2: f3 combine (128t) || am2 (32t, 4x4) || al2 (32t, 4x4) ========
        if (tid < 128) {
            float r8[8] = {0,0,0,0,0,0,0,0};
            #pragma unroll
            for (int s = 0; s < 4; ++s) {
                float4 c0 = ldchunk_f(cb, (s * 128 + tid) * 2);
                float4 c1 = ldchunk_f(cb, (s * 128 + tid) * 2 + 1);
                r8[0]+=c0.x; r8[1]+=c0.y; r8[2]+=c0.z; r8[3]+=c0.w;
                r8[4]+=c1.x; r8[5]+=c1.y; r8[6]+=c1.z; r8[7]+=c1.w;
            }
            float b = fb3[tid];
            #pragma unroll
            for (int m = 0; m < 8; ++m) r8[m] += b;
            store_row8(fo, tid, r8);
        } else if (tid < 160) {
            int u = tid - 128, h = u & 1, cg = u >> 1, j4 = 4 * cg;
            gaccum44(v, a1m, amw2, SHD, j4, h, 0, SHD);
            float4 b = reinterpret_cast<const float4*>(amb2)[cg];
            float bb[4] = {b.x, b.y, b.z, b.w};
            #pragma unroll
            for (int c = 0; c < 4; ++c)
                #pragma unroll
                for (int q = 0; q < 4; ++q) v[c*4+q] = fmaxf(v[c*4+q] + bb[c], 0.f);
            store4(a2m, j4, h, v);
        } else if (tid < 192) {
            int u = tid - 160, h = u & 1, cg = u >> 1, j4 = 4 * cg;
            gaccum44(v, a1l, alw2, SHD, j4, h, 0, SHD);
            float4 b = reinterpret_cast<const float4*>(alb2)[cg];
            float bb[4] = {b.x, b.y, b.z, b.w};
            #pragma unroll
            for (int c = 0; c < 4; ++c)
                #pragma unroll
                for (int q = 0; q < 4; ++q) v[c*4+q] = fmaxf(v[c*4+q] + bb[c], 0.f);
            store4(a2l, j4, h, v);
        }
        __syncthreads();

        // ======== Stage C3: am3 (128t, 4x4, Ksplit2) || al3 (128t, 4x4, Ksplit2); partials to cb ========
        if (tid < 128) {
            int s = tid >> 6, u = tid & 63, h = u & 1, cg = u >> 1, j4 = 4 * cg;
            gaccum44(v, a2m, amw3, ND, j4, h, s * 32, 32);
            store4(cb, s * 128 + j4, h, v);
        } else {
            int t = tid - 128, s = t >> 6, u = t & 63, h = u & 1, cg = u >> 1, j4 = 4 * cg;
            gaccum44(v, a2l, alw3, ND, j4, h, s * 32, 32);
            store4(cb, 256 + s * 128 + j4, h, v);
        }
        __syncthreads();

        // ======== Stage E: combine am3/al3, g, f+g, u_f, u_g ========
        {
            float4 kv = ldchunk_f(ko,  ewj * 2 + ewc);
            float4 fv = ldchunk_f(fo,  ewj * 2 + ewc);
            float4 m0 = ldchunk_f(cb, ewj * 2 + ewc);
            float4 m1 = ldchunk_f(cb, (128 + ewj) * 2 + ewc);
            float4 l0 = ldchunk_f(cb, (256 + ewj) * 2 + ewc);
            float4 l1 = ldchunk_f(cb, (384 + ewj) * 2 + ewc);
            float bam = amb3[ewj], bal = alb3[ewj];
            float kk[4] = {kv.x, kv.y, kv.z, kv.w};
            float ff[4] = {fv.x, fv.y, fv.z, fv.w};
            float mm[4] = {m0.x + m1.x + bam, m0.y + m1.y + bam,
                           m0.z + m1.z + bam, m0.w + m1.w + bam};
            float ll[4] = {l0.x + l1.x + bal, l0.y + l1.y + bal,
                           l0.z + l1.z + bal, l0.w + l1.w + bal};
            float gs[4], uf[4], ug[4];
            #pragma unroll
            for (int q = 0; q < 4; ++q) {
                float m = fast_tanh(mm[q]);
                float sd = fast_softplus(san(ll[q]));
                float g = fast_tanh(san(m) + sd * nse[q]);
                float om = 1.f - kk[q] * kk[q];
                gs[q] = ff[q] + g;
                uf[q] = om * ff[q];
                ug[q] = om * g;
            }
            stchunk_f(go,  ewj * 2 + ewc, make_float4(gs[0], gs[1], gs[2], gs[3]));
            stchunk_f(ubf, ewj * 2 + ewc, make_float4(uf[0], uf[1], uf[2], uf[3]));
            stchunk_f(ubg, ewj * 2 + ewc, make_float4(ug[0], ug[1], ug[2], ug[3]));
        }
        __syncthreads();

        // ======== Stage F: jacf (128t) || jacg (128t), 4x4, 2 warp-uniform K-splits ========
        if (tid < 128) {
            int s = tid >> 6, u = tid & 63, h = u & 1, cg = u >> 1, j4 = 4 * cg;
            gaccum44(v, ubf, kw, ND, j4, h, s * 64, 64);
            store4(cb, s * 128 + j4, h, v);
        } else {
            int t = tid - 128, s = t >> 6, u = t & 63, h = u & 1, cg = u >> 1, j4 = 4 * cg;
            gaccum44(v, ubg, kw, ND, j4, h, s * 64, 64);
            store4(cb, 256 + s * 128 + j4, h, v);
        }
        __syncthreads();

        // ======== Stage F2: combine + reduce ========
        if (tid < 128) {
            float va[8], wa[8];
            load_row8(cb, tid, va); load_row8(cb, 128 + tid, wa);
            float sq[8];
            #pragma unroll
            for (int m = 0; m < 8; ++m) { float x = va[m] + wa[m]; sq[m] = x * x; }
            warp_reduce8(sq);
            if ((tid & 31) == 0) {
                int w = tid >> 5;
                #pragma unroll
                for (int m = 0; m < 8; ++m) redf[w * 8 + m] = sq[m];
            }
        } else {
            int col = tid - 128;
            float va[8], wa[8], kr[8];
            load_row8(cb, 256 + col, va); load_row8(cb, 384 + col, wa);
            load_row8(ko, col, kr);
            float sq[8];
            #pragma unroll
            for (int m = 0; m < 8; ++m) sq[m] = (va[m] + wa[m]) * kr[m];
            warp_reduce8(sq);
            if ((tid & 31) == 0) {
                int w = (tid - 128) >> 5;
                #pragma unroll
                for (int m = 0; m < 8; ++m) redg[w * 8 + m] = sq[m];
            }
        }
        __syncthreads();

        // ======== Update: inline mask + Euler + output ========
        {
            float sclq[4];
            #pragma unroll
            for (int q = 0; q < 4; ++q) {
                int m = 4 * ewc + q;
                float kn2 = kn2s[m];
                float jf2 = redf[m] + redf[8 + m] + redf[16 + m] + redf[24 + m];
                float c2v = redg[m] + redg[8 + m] + redg[16 + m] + redg[24 + m];
                float kn = sqrtf(kn2);
                float kn9 = kn2 * kn2 * kn2 * kn2 * kn;
                float c1 = sqrtf(jf2) - 60.0f * kn9;
                float c2 = c2v - 20.0f * kn9 * kn;
                bool mask = (c1 > 1e-8f) || (c2 < -1e-8f);
                sclq[q] = mask ? (0.5f * dt) : dt;
            }
            float4 xv = ldchunk_f(xs, ewj * 2 + ewc);
            float4 dv = ldchunk_f(go, ewj * 2 + ewc);
            float x[4] = {xv.x, xv.y, xv.z, xv.w};
            float d[4] = {dv.x, dv.y, dv.z, dv.w};
            float o[4];
            float* ob = out + (size_t)(step + 1) * BSZ * ND;
            #pragma unroll
            for (int q = 0; q < 4; ++q) {
                int m = 4 * ewc + q;
                o[q] = x[q] + d[q] * sclq[q];
                ob[(size_t)(r0 + m) * ND + ewj] = o[q];
            }
            stchunk_f(xs, ewj * 2 + ewc, make_float4(o[0], o[1], o[2], o[3]));
        }
        __syncthreads();
    }
}

extern "C" void kernel_launch(void* const* d_in, const int* in_sizes, int n_in,
                              void* d_out, int out_size) {
    (void)in_sizes; (void)n_in; (void)out_size;
    const float* y0   = (const float*)d_in[0];
    const float* tv   = (const float*)d_in[1];
    const float* nz   = (const float*)d_in[2];
    const float* fw1  = (const float*)d_in[3];
    const float* fb1  = (const float*)d_in[4];
    const float* fw2  = (const float*)d_in[5];
    const float* fb2  = (const float*)d_in[6];
    const float* fw3  = (const float*)d_in[7];
    const float* fb3  = (const float*)d_in[8];
    const float* amw1 = (const float*)d_in[9];
    const float* amb1 = (const float*)d_in[10];
    const float* amw2 = (const float*)d_in[11];
    const float* amb2 = (const float*)d_in[12];
    const float* amw3 = (const float*)d_in[13];
    const float* amb3 = (const float*)d_in[14];
    const float* alw1 = (const float*)d_in[15];
    const float* alb1 = (const float*)d_in[16];
    const float* alw2 = (const float*)d_in[17];
    const float* alb2 = (const float*)d_in[18];
    const float* alw3 = (const float*)d_in[19];
    const float* alb3 = (const float*)d_in[20];
    const float* kw   = (const float*)d_in[21];
    float* out = (float*)d_out;

    const int shmem = 20568 * sizeof(float);  // ~82.3 KB -> 2 blocks/SM
    cudaFuncSetAttribute(node_kernel, cudaFuncAttributeMaxDynamicSharedMemorySize, shmem);
    node_kernel<<<NBLOCKS, NTHR, shmem>>>(
        y0, tv, nz, fw1, fb1, fw2, fb2, fw3, fb3,
        amw1, amb1, amw2, amb2, amw3, amb3,
        alw1, alb1, alw2, alb2, alw3, alb3, kw, out);
}